// round 6
// baseline (speedup 1.0000x reference)
#include <cuda_runtime.h>
#include <cstdint>

// Problem constants: N=50000, D_IN=256, D_OUT=128, DEG=16
#define D_IN   256
#define D_OUT  128
#define BM     192
#define TPB    512
#define PAD_N  50112   // 261 * 192: GEMM stores need no tail guard

// Scratch for Xp = X @ W — __device__ global, no allocation. Rows >= M are
// garbage but never read (column indices < M).
__device__ __align__(16) float g_Xp[(size_t)PAD_N * D_OUT];

// ---------------------------------------------------------------------------
// Packed f32x2 helpers (sm_100+ base PTX; ptxas keeps FFMA2 in SASS)
// ---------------------------------------------------------------------------
__device__ __forceinline__ unsigned long long pack_dup(float a) {
    unsigned long long r;
    asm("mov.b64 %0, {%1, %1};" : "=l"(r) : "f"(a));
    return r;
}
__device__ __forceinline__ void fma2(unsigned long long& acc,
                                     unsigned long long a, unsigned long long b) {
    asm("fma.rn.f32x2 %0, %1, %2, %0;" : "+l"(acc) : "l"(a), "l"(b));
}
__device__ __forceinline__ void unpack2(float& lo, float& hi, unsigned long long v) {
    asm("mov.b64 {%0, %1}, %2;" : "=f"(lo), "=f"(hi) : "l"(v));
}

// ---------------------------------------------------------------------------
// Kernel 1: f32x2 SGEMM  Xp[M x 128] = A[M x 256] * B[256 x 128]
// BM=192, BN=128, BK=32; 512 threads, occ 1 (1.76 waves -> 88% util).
// Micro-tile 6x8 per thread as 6x4 packed pairs. Register-prefetch pipeline.
// Warp mapping: 2 A row-slabs (broadcast LDS) x 16 B col-slabs (128B wavefront).
// ---------------------------------------------------------------------------
__global__ __launch_bounds__(TPB, 1)
void gemm_f32x2_kernel(const float* __restrict__ A, const float* __restrict__ B, int M) {
    __shared__ float As[BM][36];      // row-major, stride 36 (144B: 16B-aligned, conflict-free)
    __shared__ float Bs[32][D_OUT];   // row-major

    const int tid = threadIdx.x;
    const int m0  = blockIdx.x * BM;
    const int rs  = (tid >> 4) * 6;   // row base within tile (0..186)
    const int cc  = (tid & 15) * 8;   // col base (0..120)

    unsigned long long acc[6][4];
#pragma unroll
    for (int i = 0; i < 6; i++)
#pragma unroll
        for (int j = 0; j < 4; j++) acc[i][j] = 0ull;

    float4 pa[3], pb[2];

    // ---- prefetch chunk 0 into registers
    {
        const float* Ab = A + (size_t)m0 * D_IN;
#pragma unroll
        for (int t = 0; t < 3; t++) {
            int i = tid + t * TPB;     // 0..1535 float4 slots (192 rows x 8)
            int r = i >> 3;
            int c = (i & 7) * 4;
            pa[t] = (m0 + r < M) ? *reinterpret_cast<const float4*>(&Ab[(size_t)r * D_IN + c])
                                 : make_float4(0.f, 0.f, 0.f, 0.f);
        }
#pragma unroll
        for (int t = 0; t < 2; t++) {
            int i = tid + t * TPB;     // 0..1023 (32 rows x 32)
            int r = i >> 5;
            int c = (i & 31) * 4;
            pb[t] = *reinterpret_cast<const float4*>(&B[(size_t)r * D_OUT + c]);
        }
    }
    // ---- store chunk 0 to smem
#pragma unroll
    for (int t = 0; t < 3; t++) {
        int i = tid + t * TPB; int r = i >> 3; int c = (i & 7) * 4;
        *reinterpret_cast<float4*>(&As[r][c]) = pa[t];
    }
#pragma unroll
    for (int t = 0; t < 2; t++) {
        int i = tid + t * TPB; int r = i >> 5; int c = (i & 31) * 4;
        *reinterpret_cast<float4*>(&Bs[r][c]) = pb[t];
    }
    __syncthreads();

    for (int ch = 0; ch < 8; ch++) {
        // ---- prefetch next chunk (LDGs overlap the compute below)
        if (ch < 7) {
            const float* Ab = A + (size_t)m0 * D_IN + (ch + 1) * 32;
#pragma unroll
            for (int t = 0; t < 3; t++) {
                int i = tid + t * TPB; int r = i >> 3; int c = (i & 7) * 4;
                pa[t] = (m0 + r < M) ? *reinterpret_cast<const float4*>(&Ab[(size_t)r * D_IN + c])
                                     : make_float4(0.f, 0.f, 0.f, 0.f);
            }
            const float* Bb = B + (size_t)(ch + 1) * 32 * D_OUT;
#pragma unroll
            for (int t = 0; t < 2; t++) {
                int i = tid + t * TPB; int r = i >> 5; int c = (i & 31) * 4;
                pb[t] = *reinterpret_cast<const float4*>(&Bb[(size_t)r * D_OUT + c]);
            }
        }

        // ---- compute on current smem tiles
#pragma unroll 4
        for (int k = 0; k < 32; k++) {
            unsigned long long a2[6];
#pragma unroll
            for (int j = 0; j < 6; j++) a2[j] = pack_dup(As[rs + j][k]);
            const unsigned long long* brow =
                reinterpret_cast<const unsigned long long*>(&Bs[k][cc]);
            unsigned long long b2[4] = {brow[0], brow[1], brow[2], brow[3]};
#pragma unroll
            for (int i = 0; i < 6; i++)
#pragma unroll
                for (int j = 0; j < 4; j++)
                    fma2(acc[i][j], a2[i], b2[j]);
        }
        __syncthreads();

        // ---- store prefetched chunk
        if (ch < 7) {
#pragma unroll
            for (int t = 0; t < 3; t++) {
                int i = tid + t * TPB; int r = i >> 3; int c = (i & 7) * 4;
                *reinterpret_cast<float4*>(&As[r][c]) = pa[t];
            }
#pragma unroll
            for (int t = 0; t < 2; t++) {
                int i = tid + t * TPB; int r = i >> 5; int c = (i & 31) * 4;
                *reinterpret_cast<float4*>(&Bs[r][c]) = pb[t];
            }
            __syncthreads();
        }
    }

    // ---- epilogue: 6 rows x 8 cols per thread (scratch padded: no guard)
#pragma unroll
    for (int i = 0; i < 6; i++) {
        const int row = m0 + rs + i;
        float r[8];
#pragma unroll
        for (int j = 0; j < 4; j++) unpack2(r[2 * j], r[2 * j + 1], acc[i][j]);
        float4* dst = reinterpret_cast<float4*>(&g_Xp[(size_t)row * D_OUT + cc]);
        dst[0] = make_float4(r[0], r[1], r[2], r[3]);
        dst[1] = make_float4(r[4], r[5], r[6], r[7]);
    }
}

// ---------------------------------------------------------------------------
// Kernel 2: SpMM  out[i] = sum_{e in row i} Xp[col[e]]  (unchanged: 27 us)
// One warp per row; lane owns one float4 (4 of 128 cols). Unroll-by-8 for MLP.
// ---------------------------------------------------------------------------
__global__ void __launch_bounds__(256)
spmm_kernel(const int* __restrict__ rowptr, const int* __restrict__ colidx,
            float* __restrict__ out, int M) {
    const int warp = (blockIdx.x * blockDim.x + threadIdx.x) >> 5;
    const int lane = threadIdx.x & 31;
    if (warp >= M) return;

    const int start = __ldg(&rowptr[warp]);
    const int end   = __ldg(&rowptr[warp + 1]);

    const float4* __restrict__ Xp4 = reinterpret_cast<const float4*>(g_Xp);

    float4 acc = make_float4(0.f, 0.f, 0.f, 0.f);
    int e = start;
    for (; e + 8 <= end; e += 8) {
        int c0 = __ldg(&colidx[e + 0]);
        int c1 = __ldg(&colidx[e + 1]);
        int c2 = __ldg(&colidx[e + 2]);
        int c3 = __ldg(&colidx[e + 3]);
        int c4 = __ldg(&colidx[e + 4]);
        int c5 = __ldg(&colidx[e + 5]);
        int c6 = __ldg(&colidx[e + 6]);
        int c7 = __ldg(&colidx[e + 7]);
        float4 v0 = Xp4[(size_t)c0 * 32 + lane];
        float4 v1 = Xp4[(size_t)c1 * 32 + lane];
        float4 v2 = Xp4[(size_t)c2 * 32 + lane];
        float4 v3 = Xp4[(size_t)c3 * 32 + lane];
        float4 v4 = Xp4[(size_t)c4 * 32 + lane];
        float4 v5 = Xp4[(size_t)c5 * 32 + lane];
        float4 v6 = Xp4[(size_t)c6 * 32 + lane];
        float4 v7 = Xp4[(size_t)c7 * 32 + lane];
        acc.x += (v0.x + v1.x) + (v2.x + v3.x) + (v4.x + v5.x) + (v6.x + v7.x);
        acc.y += (v0.y + v1.y) + (v2.y + v3.y) + (v4.y + v5.y) + (v6.y + v7.y);
        acc.z += (v0.z + v1.z) + (v2.z + v3.z) + (v4.z + v5.z) + (v6.z + v7.z);
        acc.w += (v0.w + v1.w) + (v2.w + v3.w) + (v4.w + v5.w) + (v6.w + v7.w);
    }
    for (; e < end; e++) {
        int c = __ldg(&colidx[e]);
        float4 v = Xp4[(size_t)c * 32 + lane];
        acc.x += v.x; acc.y += v.y; acc.z += v.z; acc.w += v.w;
    }

    reinterpret_cast<float4*>(out)[(size_t)warp * 32 + lane] = acc;
}

// ---------------------------------------------------------------------------
// Launch. Inputs (metadata order): X, weights, row_pointers, column_index, ...
// ---------------------------------------------------------------------------
extern "C" void kernel_launch(void* const* d_in, const int* in_sizes, int n_in,
                              void* d_out, int out_size) {
    const float* X  = (const float*)d_in[0];
    const float* W  = (const float*)d_in[1];
    const int*   rp = (const int*)d_in[2];
    const int*   ci = (const int*)d_in[3];
    float* out = (float*)d_out;

    const int M = in_sizes[0] / D_IN;   // 50000

    dim3 gemm_grid((M + BM - 1) / BM);  // 261
    gemm_f32x2_kernel<<<gemm_grid, TPB>>>(X, W, M);

    const int warps_per_block = 256 / 32;
    dim3 spmm_grid((M + warps_per_block - 1) / warps_per_block);
    spmm_kernel<<<spmm_grid, 256>>>(rp, ci, out, M);
}

// round 7
// speedup vs baseline: 1.1685x; 1.1685x over previous
#include <cuda_runtime.h>
#include <cstdint>

// Problem constants: N=50000, D_IN=256, D_OUT=128, DEG=16
#define D_IN   256
#define D_OUT  128
#define BM     128
#define BKC    16
#define NCH    (D_IN / BKC)   // 16
#define PAD_N  50048          // 391 * 128: GEMM stores need no tail guard

// Scratch for Xp = X @ W — __device__ global, no allocation. Rows >= M are
// garbage but never read (column indices < M).
__device__ __align__(16) float g_Xp[(size_t)PAD_N * D_OUT];

// ---------------------------------------------------------------------------
// Packed f32x2 + cp.async helpers
// ---------------------------------------------------------------------------
__device__ __forceinline__ unsigned long long pack_dup(float a) {
    unsigned long long r;
    asm("mov.b64 %0, {%1, %1};" : "=l"(r) : "f"(a));
    return r;
}
__device__ __forceinline__ void fma2(unsigned long long& acc,
                                     unsigned long long a, unsigned long long b) {
    asm("fma.rn.f32x2 %0, %1, %2, %0;" : "+l"(acc) : "l"(a), "l"(b));
}
__device__ __forceinline__ void unpack2(float& lo, float& hi, unsigned long long v) {
    asm("mov.b64 {%0, %1}, %2;" : "=f"(lo), "=f"(hi) : "l"(v));
}
__device__ __forceinline__ uint32_t smem_u32(const void* p) {
    uint32_t a;
    asm("{ .reg .u64 t; cvta.to.shared.u64 t, %1; cvt.u32.u64 %0, t; }"
        : "=r"(a) : "l"(p));
    return a;
}
__device__ __forceinline__ void cp16(uint32_t dst, const void* src) {
    asm volatile("cp.async.cg.shared.global [%0], [%1], 16;"
                 :: "r"(dst), "l"(src) : "memory");
}
__device__ __forceinline__ void cp_commit() {
    asm volatile("cp.async.commit_group;" ::: "memory");
}
template <int N>
__device__ __forceinline__ void cp_wait() {
    asm volatile("cp.async.wait_group %0;" :: "n"(N) : "memory");
}

// ---------------------------------------------------------------------------
// Kernel 1: f32x2 SGEMM  Xp[M x 128] = A[M x 256] * B[256 x 128]
// BM=128, BN=128, BK=16; 256 threads, occ 2. cp.async double buffer.
// Micro-tile 8x8 per thread as 8x4 packed pairs (FFMA2).
// ---------------------------------------------------------------------------
__global__ __launch_bounds__(256, 2)
void gemm_f32x2_kernel(const float* __restrict__ A, const float* __restrict__ B, int M) {
    __shared__ float As[2][BM][BKC];     // row-major, 64B rows
    __shared__ float Bs[2][BKC][D_OUT];  // row-major

    const int tid = threadIdx.x;         // 0..255
    const int m0  = blockIdx.x * BM;
    const int ty  = tid >> 4;            // 0..15 -> 8-row slab
    const int tx  = tid & 15;            // 0..15 -> 8-col slab

    // Per-thread staging coordinates (2 float4 for A, 2 for B per chunk)
    const int ar0 = tid >> 2;                  // A: thread covers row ar0 (+128 variant)
    const int ac0 = (tid & 3) * 4;             //    float4 col within 16
    // A tile has 512 float4: i = tid + t*256 -> r = i>>2, c4 = i&3

    unsigned long long acc[8][4];
#pragma unroll
    for (int i = 0; i < 8; i++)
#pragma unroll
        for (int j = 0; j < 4; j++) acc[i][j] = 0ull;

    // ---- stage chunk 0 into buffer 0
    {
#pragma unroll
        for (int t = 0; t < 2; t++) {
            int i = tid + t * 256;             // 0..511
            int r = i >> 2;
            int c = (i & 3) * 4;
            uint32_t dst = smem_u32(&As[0][r][c]);
            if (m0 + r < M) cp16(dst, &A[(size_t)(m0 + r) * D_IN + c]);
            else *reinterpret_cast<float4*>(&As[0][r][c]) = make_float4(0.f, 0.f, 0.f, 0.f);
        }
#pragma unroll
        for (int t = 0; t < 2; t++) {
            int i = tid + t * 256;             // 0..511
            int r = i >> 5;                    // 0..15
            int c = (i & 31) * 4;
            cp16(smem_u32(&Bs[0][r][c]), &B[(size_t)r * D_OUT + c]);
        }
        cp_commit();
    }

    for (int ch = 0; ch < NCH; ch++) {
        const int cur = ch & 1;
        // ---- stage next chunk into the other buffer (overlaps compute)
        if (ch < NCH - 1) {
            const int nxt = cur ^ 1;
            const int k0  = (ch + 1) * BKC;
#pragma unroll
            for (int t = 0; t < 2; t++) {
                int i = tid + t * 256;
                int r = i >> 2;
                int c = (i & 3) * 4;
                uint32_t dst = smem_u32(&As[nxt][r][c]);
                if (m0 + r < M) cp16(dst, &A[(size_t)(m0 + r) * D_IN + k0 + c]);
                else *reinterpret_cast<float4*>(&As[nxt][r][c]) = make_float4(0.f, 0.f, 0.f, 0.f);
            }
#pragma unroll
            for (int t = 0; t < 2; t++) {
                int i = tid + t * 256;
                int r = i >> 5;
                int c = (i & 31) * 4;
                cp16(smem_u32(&Bs[nxt][r][c]), &B[(size_t)(k0 + r) * D_OUT + c]);
            }
            cp_commit();
            cp_wait<1>();      // current chunk's group has landed
        } else {
            cp_wait<0>();
        }
        __syncthreads();

        // ---- compute on current buffer
#pragma unroll
        for (int k = 0; k < BKC; k++) {
            unsigned long long a2[8];
#pragma unroll
            for (int j = 0; j < 8; j++) a2[j] = pack_dup(As[cur][ty * 8 + j][k]);
            ulonglong2 bb0 = *reinterpret_cast<const ulonglong2*>(&Bs[cur][k][tx * 8]);
            ulonglong2 bb1 = *reinterpret_cast<const ulonglong2*>(&Bs[cur][k][tx * 8 + 4]);
            unsigned long long b2[4] = {bb0.x, bb0.y, bb1.x, bb1.y};
#pragma unroll
            for (int i = 0; i < 8; i++)
#pragma unroll
                for (int j = 0; j < 4; j++)
                    fma2(acc[i][j], a2[i], b2[j]);
        }
        __syncthreads();       // protect buffer reuse by next iteration's staging
    }

    // ---- epilogue: 8 rows x 8 cols per thread (scratch padded: no guard)
#pragma unroll
    for (int i = 0; i < 8; i++) {
        const int row = m0 + ty * 8 + i;
        float r[8];
#pragma unroll
        for (int j = 0; j < 4; j++) unpack2(r[2 * j], r[2 * j + 1], acc[i][j]);
        float4* dst = reinterpret_cast<float4*>(&g_Xp[(size_t)row * D_OUT + tx * 8]);
        dst[0] = make_float4(r[0], r[1], r[2], r[3]);
        dst[1] = make_float4(r[4], r[5], r[6], r[7]);
    }
    (void)ar0; (void)ac0;
}

// ---------------------------------------------------------------------------
// Kernel 2: SpMM  out[i] = sum_{e in row i} Xp[col[e]]  (unchanged: ~27 us)
// One warp per row; lane owns one float4 (4 of 128 cols). Unroll-by-8 for MLP.
// ---------------------------------------------------------------------------
__global__ void __launch_bounds__(256)
spmm_kernel(const int* __restrict__ rowptr, const int* __restrict__ colidx,
            float* __restrict__ out, int M) {
    const int warp = (blockIdx.x * blockDim.x + threadIdx.x) >> 5;
    const int lane = threadIdx.x & 31;
    if (warp >= M) return;

    const int start = __ldg(&rowptr[warp]);
    const int end   = __ldg(&rowptr[warp + 1]);

    const float4* __restrict__ Xp4 = reinterpret_cast<const float4*>(g_Xp);

    float4 acc = make_float4(0.f, 0.f, 0.f, 0.f);
    int e = start;
    for (; e + 8 <= end; e += 8) {
        int c0 = __ldg(&colidx[e + 0]);
        int c1 = __ldg(&colidx[e + 1]);
        int c2 = __ldg(&colidx[e + 2]);
        int c3 = __ldg(&colidx[e + 3]);
        int c4 = __ldg(&colidx[e + 4]);
        int c5 = __ldg(&colidx[e + 5]);
        int c6 = __ldg(&colidx[e + 6]);
        int c7 = __ldg(&colidx[e + 7]);
        float4 v0 = Xp4[(size_t)c0 * 32 + lane];
        float4 v1 = Xp4[(size_t)c1 * 32 + lane];
        float4 v2 = Xp4[(size_t)c2 * 32 + lane];
        float4 v3 = Xp4[(size_t)c3 * 32 + lane];
        float4 v4 = Xp4[(size_t)c4 * 32 + lane];
        float4 v5 = Xp4[(size_t)c5 * 32 + lane];
        float4 v6 = Xp4[(size_t)c6 * 32 + lane];
        float4 v7 = Xp4[(size_t)c7 * 32 + lane];
        acc.x += (v0.x + v1.x) + (v2.x + v3.x) + (v4.x + v5.x) + (v6.x + v7.x);
        acc.y += (v0.y + v1.y) + (v2.y + v3.y) + (v4.y + v5.y) + (v6.y + v7.y);
        acc.z += (v0.z + v1.z) + (v2.z + v3.z) + (v4.z + v5.z) + (v6.z + v7.z);
        acc.w += (v0.w + v1.w) + (v2.w + v3.w) + (v4.w + v5.w) + (v6.w + v7.w);
    }
    for (; e < end; e++) {
        int c = __ldg(&colidx[e]);
        float4 v = Xp4[(size_t)c * 32 + lane];
        acc.x += v.x; acc.y += v.y; acc.z += v.z; acc.w += v.w;
    }

    reinterpret_cast<float4*>(out)[(size_t)warp * 32 + lane] = acc;
}

// ---------------------------------------------------------------------------
// Launch. Inputs (metadata order): X, weights, row_pointers, column_index, ...
// ---------------------------------------------------------------------------
extern "C" void kernel_launch(void* const* d_in, const int* in_sizes, int n_in,
                              void* d_out, int out_size) {
    const float* X  = (const float*)d_in[0];
    const float* W  = (const float*)d_in[1];
    const int*   rp = (const int*)d_in[2];
    const int*   ci = (const int*)d_in[3];
    float* out = (float*)d_out;

    const int M = in_sizes[0] / D_IN;   // 50000

    dim3 gemm_grid((M + BM - 1) / BM);  // 391
    gemm_f32x2_kernel<<<gemm_grid, 256>>>(X, W, M);

    const int warps_per_block = 256 / 32;
    dim3 spmm_grid((M + warps_per_block - 1) / warps_per_block);
    spmm_kernel<<<spmm_grid, 256>>>(rp, ci, out, M);
}

// round 9
// speedup vs baseline: 1.2013x; 1.0280x over previous
#include <cuda_runtime.h>
#include <cstdint>

// Problem constants: N=50000, D_IN=256, D_OUT=128, DEG=16
#define D_IN   256
#define D_OUT  128
#define BM     128
#define BKC    16
#define NCH    (D_IN / BKC)   // 16
#define STAGES 4
#define STAGE_FLOATS 4096     // A(128x16) + B(16x128) = 2048 + 2048 floats = 16KB
#define SMEM_BYTES  (STAGES * STAGE_FLOATS * 4)   // 64KB
#define PAD_N  50048          // 391 * 128: GEMM stores need no tail guard

// Scratch for Xp = X @ W — __device__ global, no allocation. Rows >= M are
// garbage but never read (column indices < M).
__device__ __align__(16) float g_Xp[(size_t)PAD_N * D_OUT];

// ---------------------------------------------------------------------------
// Packed f32x2 + cp.async helpers
// ---------------------------------------------------------------------------
__device__ __forceinline__ unsigned long long pack_dup(float a) {
    unsigned long long r;
    asm("mov.b64 %0, {%1, %1};" : "=l"(r) : "f"(a));
    return r;
}
__device__ __forceinline__ void fma2(unsigned long long& acc,
                                     unsigned long long a, unsigned long long b) {
    asm("fma.rn.f32x2 %0, %1, %2, %0;" : "+l"(acc) : "l"(a), "l"(b));
}
__device__ __forceinline__ void unpack2(float& lo, float& hi, unsigned long long v) {
    asm("mov.b64 {%0, %1}, %2;" : "=f"(lo), "=f"(hi) : "l"(v));
}
__device__ __forceinline__ uint32_t smem_u32(const void* p) {
    uint32_t a;
    asm("{ .reg .u64 t; cvta.to.shared.u64 t, %1; cvt.u32.u64 %0, t; }"
        : "=r"(a) : "l"(p));
    return a;
}
// 16B cp.async with zero-fill when src_sz == 0 (OOB rows)
__device__ __forceinline__ void cp16z(uint32_t dst, const void* src, int src_sz) {
    asm volatile("cp.async.cg.shared.global [%0], [%1], 16, %2;"
                 :: "r"(dst), "l"(src), "r"(src_sz) : "memory");
}
__device__ __forceinline__ void cp_commit() {
    asm volatile("cp.async.commit_group;" ::: "memory");
}
template <int N>
__device__ __forceinline__ void cp_wait() {
    asm volatile("cp.async.wait_group %0;" :: "n"(N) : "memory");
}

// ---------------------------------------------------------------------------
// Kernel 1: f32x2 SGEMM  Xp[M x 128] = A[M x 256] * B[256 x 128]
// BM=128, BN=128, BK=16; 256 threads, occ 2. 4-stage cp.async pipeline,
// ONE __syncthreads per chunk. Micro-tile 8x8 as 8x4 packed pairs (FFMA2).
// A consumed as float2 k-pairs (half the LDS ops of scalar reads).
// ---------------------------------------------------------------------------
extern __shared__ float s_pipe[];

__global__ __launch_bounds__(256, 2)
void gemm_f32x2_kernel(const float* __restrict__ A, const float* __restrict__ B, int M) {
    const int tid = threadIdx.x;         // 0..255
    const int m0  = blockIdx.x * BM;
    const int ty  = tid >> 4;            // 0..15 -> 8-row slab
    const int tx  = tid & 15;            // 0..15 -> 8-col slab

    unsigned long long acc[8][4];
#pragma unroll
    for (int i = 0; i < 8; i++)
#pragma unroll
        for (int j = 0; j < 4; j++) acc[i][j] = 0ull;

    // staging lambda replacement (macro-ish inline): chunk ch -> stage buffer s
    auto stage_chunk = [&](int ch) {
        float* buf = s_pipe + (ch & 3) * STAGE_FLOATS;
        const int k0 = ch * BKC;
        // A: 512 float4, 2 per thread. As[r][c] row-major stride 16.
#pragma unroll
        for (int t = 0; t < 2; t++) {
            int i = tid + t * 256;               // 0..511
            int r = i >> 2;                      // 0..127
            int c = (i & 3) * 4;                 // 0,4,8,12
            int ok = (m0 + r < M) ? 16 : 0;
            cp16z(smem_u32(&buf[r * BKC + c]),
                  &A[(size_t)(m0 + r) * D_IN + k0 + c], ok);
        }
        // B: 512 float4, 2 per thread. Bs[r][c] row-major stride 128, at offset 2048.
        float* bb = buf + BM * BKC;
#pragma unroll
        for (int t = 0; t < 2; t++) {
            int i = tid + t * 256;               // 0..511
            int r = i >> 5;                      // 0..15
            int c = (i & 31) * 4;
            cp16z(smem_u32(&bb[r * D_OUT + c]),
                  &B[(size_t)(k0 + r) * D_OUT + c], 16);
        }
        cp_commit();
    };

    // ---- prologue: stage chunks 0..2
    stage_chunk(0);
    stage_chunk(1);
    stage_chunk(2);

    for (int ch = 0; ch < NCH; ch++) {
        cp_wait<2>();            // chunk ch has landed
        __syncthreads();         // all warps agree buffers are ready / reusable

        const float* As = s_pipe + (ch & 3) * STAGE_FLOATS;
        const float* Bs = As + BM * BKC;

#pragma unroll
        for (int k = 0; k < BKC; k += 2) {
            // A: 8 rows x 2 ks as float2 (broadcast, 2 distinct addrs/warp)
            float2 a01[8];
#pragma unroll
            for (int j = 0; j < 8; j++)
                a01[j] = *reinterpret_cast<const float2*>(&As[(ty * 8 + j) * BKC + k]);
            // k
            {
                const unsigned long long* br =
                    reinterpret_cast<const unsigned long long*>(&Bs[k * D_OUT + tx * 8]);
                unsigned long long b2[4] = {br[0], br[1], br[2], br[3]};
#pragma unroll
                for (int i = 0; i < 8; i++) {
                    unsigned long long ad = pack_dup(a01[i].x);
#pragma unroll
                    for (int j = 0; j < 4; j++) fma2(acc[i][j], ad, b2[j]);
                }
            }
            // k+1
            {
                const unsigned long long* br =
                    reinterpret_cast<const unsigned long long*>(&Bs[(k + 1) * D_OUT + tx * 8]);
                unsigned long long b2[4] = {br[0], br[1], br[2], br[3]};
#pragma unroll
                for (int i = 0; i < 8; i++) {
                    unsigned long long ad = pack_dup(a01[i].y);
#pragma unroll
                    for (int j = 0; j < 4; j++) fma2(acc[i][j], ad, b2[j]);
                }
            }
        }

        // stage chunk ch+3 (overwrites buffer of ch-1; safe: all warps passed
        // the sync for ch, hence finished computing ch-1)
        if (ch + 3 < NCH) stage_chunk(ch + 3);
    }

    // ---- epilogue: 8 rows x 8 cols per thread (scratch padded: no guard)
#pragma unroll
    for (int i = 0; i < 8; i++) {
        const int row = m0 + ty * 8 + i;
        float r[8];
#pragma unroll
        for (int j = 0; j < 4; j++) unpack2(r[2 * j], r[2 * j + 1], acc[i][j]);
        float4* dst = reinterpret_cast<float4*>(&g_Xp[(size_t)row * D_OUT + tx * 8]);
        dst[0] = make_float4(r[0], r[1], r[2], r[3]);
        dst[1] = make_float4(r[4], r[5], r[6], r[7]);
    }
}

// ---------------------------------------------------------------------------
// Kernel 2: SpMM  out[i] = sum_{e in row i} Xp[col[e]]  (unchanged: ~27 us)
// One warp per row; lane owns one float4 (4 of 128 cols). Unroll-by-8 for MLP.
// ---------------------------------------------------------------------------
__global__ void __launch_bounds__(256)
spmm_kernel(const int* __restrict__ rowptr, const int* __restrict__ colidx,
            float* __restrict__ out, int M) {
    const int warp = (blockIdx.x * blockDim.x + threadIdx.x) >> 5;
    const int lane = threadIdx.x & 31;
    if (warp >= M) return;

    const int start = __ldg(&rowptr[warp]);
    const int end   = __ldg(&rowptr[warp + 1]);

    const float4* __restrict__ Xp4 = reinterpret_cast<const float4*>(g_Xp);

    float4 acc = make_float4(0.f, 0.f, 0.f, 0.f);
    int e = start;
    for (; e + 8 <= end; e += 8) {
        int c0 = __ldg(&colidx[e + 0]);
        int c1 = __ldg(&colidx[e + 1]);
        int c2 = __ldg(&colidx[e + 2]);
        int c3 = __ldg(&colidx[e + 3]);
        int c4 = __ldg(&colidx[e + 4]);
        int c5 = __ldg(&colidx[e + 5]);
        int c6 = __ldg(&colidx[e + 6]);
        int c7 = __ldg(&colidx[e + 7]);
        float4 v0 = Xp4[(size_t)c0 * 32 + lane];
        float4 v1 = Xp4[(size_t)c1 * 32 + lane];
        float4 v2 = Xp4[(size_t)c2 * 32 + lane];
        float4 v3 = Xp4[(size_t)c3 * 32 + lane];
        float4 v4 = Xp4[(size_t)c4 * 32 + lane];
        float4 v5 = Xp4[(size_t)c5 * 32 + lane];
        float4 v6 = Xp4[(size_t)c6 * 32 + lane];
        float4 v7 = Xp4[(size_t)c7 * 32 + lane];
        acc.x += (v0.x + v1.x) + (v2.x + v3.x) + (v4.x + v5.x) + (v6.x + v7.x);
        acc.y += (v0.y + v1.y) + (v2.y + v3.y) + (v4.y + v5.y) + (v6.y + v7.y);
        acc.z += (v0.z + v1.z) + (v2.z + v3.z) + (v4.z + v5.z) + (v6.z + v7.z);
        acc.w += (v0.w + v1.w) + (v2.w + v3.w) + (v4.w + v5.w) + (v6.w + v7.w);
    }
    for (; e < end; e++) {
        int c = __ldg(&colidx[e]);
        float4 v = Xp4[(size_t)c * 32 + lane];
        acc.x += v.x; acc.y += v.y; acc.z += v.z; acc.w += v.w;
    }

    reinterpret_cast<float4*>(out)[(size_t)warp * 32 + lane] = acc;
}

// ---------------------------------------------------------------------------
// Launch. Inputs (metadata order): X, weights, row_pointers, column_index, ...
// ---------------------------------------------------------------------------
extern "C" void kernel_launch(void* const* d_in, const int* in_sizes, int n_in,
                              void* d_out, int out_size) {
    const float* X  = (const float*)d_in[0];
    const float* W  = (const float*)d_in[1];
    const int*   rp = (const int*)d_in[2];
    const int*   ci = (const int*)d_in[3];
    float* out = (float*)d_out;

    const int M = in_sizes[0] / D_IN;   // 50000

    static bool attr_set = false;
    if (!attr_set) {
        cudaFuncSetAttribute(gemm_f32x2_kernel,
                             cudaFuncAttributeMaxDynamicSharedMemorySize, SMEM_BYTES);
        attr_set = true;
    }

    dim3 gemm_grid((M + BM - 1) / BM);  // 391
    gemm_f32x2_kernel<<<gemm_grid, 256, SMEM_BYTES>>>(X, W, M);

    const int warps_per_block = 256 / 32;
    dim3 spmm_grid((M + warps_per_block - 1) / warps_per_block);
    spmm_kernel<<<spmm_grid, 256>>>(rp, ci, out, M);
}